// round 14
// baseline (speedup 1.0000x reference)
#include <cuda_runtime.h>
#include <cuda_fp16.h>
#include <cstdint>

#define NP 8192
#define DK 128
#define NTHR 256
#define NLAB 512
#define GRID 256
#define NTJ 16

__device__ __half   g_afrag[NP * DK];
__device__ __half   g_bfrag[NP * DK];
__device__ float2   g_meta[NP];         // (sq_norm, label) — label-sorted order
__device__ unsigned g_ap[NP];
__device__ unsigned g_an[NP];
__device__ int      g_bins[NLAB];
__device__ int      g_cursor[NLAB];
__device__ int      g_gsync = 0;
__device__ int      g_done  = 0;

// ---------- helpers ----------
__device__ __forceinline__ uint32_t smem_u32(const void* p) {
    uint32_t a;
    asm("{ .reg .u64 t; cvta.to.shared.u64 t, %1; cvt.u32.u64 %0, t; }"
        : "=r"(a) : "l"(p));
    return a;
}
__device__ __forceinline__ void cp16(uint32_t dst, const void* src) {
    asm volatile("cp.async.cg.shared.global [%0], [%1], 16;" :: "r"(dst), "l"(src));
}
__device__ __forceinline__ void cp8(uint32_t dst, const void* src) {
    asm volatile("cp.async.ca.shared.global [%0], [%1], 8;" :: "r"(dst), "l"(src));
}
#define CP_COMMIT() asm volatile("cp.async.commit_group;" ::: "memory")

__device__ __forceinline__ void mma_f16(float* d, const uint4& a, const uint2& b) {
    asm volatile(
        "mma.sync.aligned.m16n8k16.row.col.f32.f16.f16.f32 "
        "{%0,%1,%2,%3}, {%4,%5,%6,%7}, {%8,%9}, {%0,%1,%2,%3};"
        : "+f"(d[0]), "+f"(d[1]), "+f"(d[2]), "+f"(d[3])
        : "r"(a.x), "r"(a.y), "r"(a.z), "r"(a.w), "r"(b.x), "r"(b.y));
}

__device__ __forceinline__ void grid_sync(int target) {
    __syncthreads();
    if (threadIdx.x == 0) {
        __threadfence();
        atomicAdd(&g_gsync, 1);
        while (atomicAdd(&g_gsync, 0) < target) { }
    }
    __syncthreads();
}

// ---------- persistent prep: detect + hist + scan + counting-sort scatter ----------
__global__ void __launch_bounds__(NTHR, 2)
prep_all(const float* __restrict__ f, const int* __restrict__ lab) {
    const int t = threadIdx.x, lane = t & 31, wid = t >> 5;
    const int cta = blockIdx.x;

    int nz = (lab[2 * t + 1] != 0);
    const int l64 = !__syncthreads_or(nz);

    if (t < 32) {
        int row = cta * 32 + t;
        atomicAdd(&g_bins[lab[l64 ? (row << 1) : row]], 1);
    }
    grid_sync(GRID);

    if (cta == 0) {
        __shared__ int wsum[8];
        int b0 = g_bins[2 * t], b1 = g_bins[2 * t + 1];
        int ps = b0 + b1;
        int x = ps;
        #pragma unroll
        for (int m = 1; m < 32; m <<= 1) {
            int y = __shfl_up_sync(0xffffffffu, x, m);
            if (lane >= m) x += y;
        }
        if (lane == 31) wsum[wid] = x;
        __syncthreads();
        if (t == 0) {
            int acc = 0;
            #pragma unroll
            for (int q = 0; q < 8; ++q) { int v = wsum[q]; wsum[q] = acc; acc += v; }
        }
        __syncthreads();
        int excl = x - ps + wsum[wid];
        g_cursor[2 * t]     = excl;
        g_cursor[2 * t + 1] = excl + b0;
        g_bins[2 * t] = 0; g_bins[2 * t + 1] = 0;
    }
    grid_sync(2 * GRID);

    #pragma unroll
    for (int q = 0; q < 4; ++q) {
        int row = cta * 32 + wid * 4 + q;
        const float* p = f + (size_t)row * DK;
        int li = 0, dst = 0;
        if (lane == 0) {
            li  = lab[l64 ? (row << 1) : row];
            dst = atomicAdd(&g_cursor[li], 1);
        }
        li  = __shfl_sync(0xffffffffu, li, 0);
        dst = __shfl_sync(0xffffffffu, dst, 0);

        const int tile = dst >> 7;
        const int n    = dst & 127;
        char* abase = (char*)g_afrag + (size_t)tile * 32768;
        char* bbase = (char*)g_bfrag + (size_t)tile * 32768;
        const int wm = n >> 6, mfrag = (n >> 4) & 3, r16 = n & 15;
        const int wn = n >> 5, nfrag = (n >> 3) & 3, nn = n & 7;

        float s = 0.f;
        #pragma unroll
        for (int u = 0; u < 4; ++u) {
            int k = lane + u * 32;
            float v = p[k];
            s += v * v;
            __half hv = __float2half_rn(v);
            int ks = k >> 4, kk = k & 15;
            int lane_a = (r16 & 7) * 4 + ((kk & 7) >> 1);
            int reg_a  = ((kk >= 8) ? 2 : 0) + (r16 >> 3);
            *(__half*)(abase + ks * 4096 + wm * 2048 + mfrag * 512
                       + lane_a * 16 + reg_a * 4 + (kk & 1) * 2) = hv;
            int lane_b = nn * 4 + ((kk & 7) >> 1);
            int reg_b  = (kk >= 8) ? 1 : 0;
            *(__half*)(bbase + ks * 4096 + wn * 1024 + nfrag * 256
                       + lane_b * 8 + reg_b * 4 + (kk & 1) * 2) = hv;
        }
        #pragma unroll
        for (int m = 16; m; m >>= 1) s += __shfl_xor_sync(0xffffffffu, s, m);
        if (lane == 0) {
            g_meta[dst] = make_float2(s, (float)li);
            g_ap[dst] = 0u;
            g_an[dst] = __float_as_uint(1e12f);
        }
    }
}

// ---------- main kernel: FULL matrix, sorted labels, row-only epilogue ----------
// grid = 64 it x 4 j-quarters. ~90% of tiles are label-disjoint ("clean"):
// epilogue = pure unmasked fmin into an[] (no labels, no shuffles, no atomics).
__global__ void __launch_bounds__(NTHR, 2)
triplet_mma(float* __restrict__ out) {
    extern __shared__ char smem[];
    char*   sA  = smem;                        // 32768
    char*   sB  = smem + 32768;                // 2 x 32768
    float2* sMB = (float2*)(smem + 98304);     // 2 x 128 float2
    const uint32_t sAu  = smem_u32(sA);
    const uint32_t sBu  = smem_u32(sB);
    const uint32_t sMBu = smem_u32(sMB);

    const int t = threadIdx.x, lane = t & 31, wid = t >> 5;
    const int warp_m = wid >> 2, warp_n = wid & 3;
    const int it = blockIdx.x >> 2, jq = blockIdx.x & 3;
    const int i0  = it * 128;
    const int jt0 = jq * NTJ;

    // prologue: A tile + B tile 0 + metaB
    {
        const uint4* as = (const uint4*)((const char*)g_afrag + (size_t)it * 32768);
        #pragma unroll
        for (int u = 0; u < 8; ++u)
            cp16(sAu + (t + u * 256) * 16, as + t + u * 256);
        const uint4* bs = (const uint4*)((const char*)g_bfrag + (size_t)jt0 * 32768);
        #pragma unroll
        for (int u = 0; u < 8; ++u)
            cp16(sBu + (t + u * 256) * 16, bs + t + u * 256);
        if (t < 128) cp8(sMBu + t * 8, &g_meta[jt0 * 128 + t]);
        CP_COMMIT();
    }

    const float minI = g_meta[i0].y;
    const float maxI = g_meta[i0 + 127].y;

    float rsq[8], rlab[8];
    #pragma unroll
    for (int mf = 0; mf < 4; ++mf)
        #pragma unroll
        for (int rr = 0; rr < 2; ++rr) {
            float2 m = g_meta[i0 + warp_m * 64 + mf * 16 + rr * 8 + (lane >> 2)];
            rsq[mf * 2 + rr]  = m.x;
            rlab[mf * 2 + rr] = m.y;
        }

    float ap[8], an[8];
    #pragma unroll
    for (int r = 0; r < 8; ++r) { ap[r] = 0.f; an[r] = 1e12f; }

    for (int s = 0; s < NTJ; ++s) {
        const int jt  = jt0 + s;
        const int buf = s & 1;

        asm volatile("cp.async.wait_group 0;" ::: "memory");
        __syncthreads();

        if (s + 1 < NTJ) {
            const uint4* bs = (const uint4*)((const char*)g_bfrag
                                             + (size_t)(jt + 1) * 32768);
            uint32_t bd = sBu + (uint32_t)(buf ^ 1) * 32768u;
            #pragma unroll
            for (int u = 0; u < 8; ++u)
                cp16(bd + (t + u * 256) * 16, bs + t + u * 256);
            if (t < 128)
                cp8(sMBu + (buf ^ 1) * 1024 + t * 8, &g_meta[(jt + 1) * 128 + t]);
            CP_COMMIT();
        }

        // ---- MMA over K=128 (8 k16-steps), 4 m-frags x 4 n-frags ----
        float acc[4][4][4];
        #pragma unroll
        for (int mf = 0; mf < 4; ++mf)
            #pragma unroll
            for (int nf = 0; nf < 4; ++nf)
                #pragma unroll
                for (int e = 0; e < 4; ++e) acc[mf][nf][e] = 0.f;

        const uint4* Af = (const uint4*)sA + warp_m * 128;
        const uint2* Bf = (const uint2*)(sB + buf * 32768) + warp_n * 128;
        #pragma unroll
        for (int ks = 0; ks < 8; ++ks) {
            uint4 a[4]; uint2 b[4];
            #pragma unroll
            for (int mf = 0; mf < 4; ++mf) a[mf] = Af[ks * 256 + mf * 32 + lane];
            #pragma unroll
            for (int nf = 0; nf < 4; ++nf) b[nf] = Bf[ks * 512 + nf * 32 + lane];
            #pragma unroll
            for (int mf = 0; mf < 4; ++mf)
                #pragma unroll
                for (int nf = 0; nf < 4; ++nf)
                    mma_f16(acc[mf][nf], a[mf], b[nf]);
        }

        const float2* MB = sMB + buf * 128;
        const float minJ = MB[0].y, maxJ = MB[127].y;
        const bool clean = (jt != it) && ((maxI < minJ) || (maxJ < minI));

        if (clean) {
            // ---- CLEAN: all pairs negative, unmasked row mins only ----
            #pragma unroll
            for (int nf = 0; nf < 4; ++nf) {
                const int cl = warp_n * 32 + nf * 8 + (lane & 3) * 2;
                const float s0 = MB[cl].x;
                const float s1 = MB[cl + 1].x;
                #pragma unroll
                for (int mf = 0; mf < 4; ++mf)
                    #pragma unroll
                    for (int rr = 0; rr < 2; ++rr) {
                        const int r = mf * 2 + rr;
                        float d20 = fmaf(-2.f, acc[mf][nf][rr * 2 + 0], rsq[r] + s0);
                        float d21 = fmaf(-2.f, acc[mf][nf][rr * 2 + 1], rsq[r] + s1);
                        an[r] = fminf(an[r], fminf(d20, d21));
                    }
            }
        } else if (jt != it) {
            // ---- DIRTY off-diagonal: masked row stats ----
            #pragma unroll
            for (int nf = 0; nf < 4; ++nf) {
                const int cl = warp_n * 32 + nf * 8 + (lane & 3) * 2;
                const float2 m0 = MB[cl];
                const float2 m1 = MB[cl + 1];
                #pragma unroll
                for (int mf = 0; mf < 4; ++mf)
                    #pragma unroll
                    for (int rr = 0; rr < 2; ++rr) {
                        const int r = mf * 2 + rr;
                        float d20 = fmaf(-2.f, acc[mf][nf][rr * 2 + 0], rsq[r] + m0.x);
                        float d21 = fmaf(-2.f, acc[mf][nf][rr * 2 + 1], rsq[r] + m1.x);
                        if (rlab[r] == m0.y) ap[r] = fmaxf(ap[r], d20);
                        else                 an[r] = fminf(an[r], d20);
                        if (rlab[r] == m1.y) ap[r] = fmaxf(ap[r], d21);
                        else                 an[r] = fminf(an[r], d21);
                    }
            }
        } else {
            // ---- diagonal: masked, exclude i==j ----
            #pragma unroll
            for (int nf = 0; nf < 4; ++nf) {
                const int cl = warp_n * 32 + nf * 8 + (lane & 3) * 2;
                const float2 m0 = MB[cl];
                const float2 m1 = MB[cl + 1];
                #pragma unroll
                for (int mf = 0; mf < 4; ++mf)
                    #pragma unroll
                    for (int rr = 0; rr < 2; ++rr) {
                        const int r = mf * 2 + rr;
                        const int ri = warp_m * 64 + mf * 16 + rr * 8 + (lane >> 2);
                        float d20 = fmaf(-2.f, acc[mf][nf][rr * 2 + 0], rsq[r] + m0.x);
                        float d21 = fmaf(-2.f, acc[mf][nf][rr * 2 + 1], rsq[r] + m1.x);
                        if (rlab[r] == m0.y) {
                            if (ri != cl) ap[r] = fmaxf(ap[r], d20);
                        } else an[r] = fminf(an[r], d20);
                        if (rlab[r] == m1.y) {
                            if (ri != cl + 1) ap[r] = fmaxf(ap[r], d21);
                        } else an[r] = fminf(an[r], d21);
                    }
            }
        }
    }

    // ---- row-stat reduce (lanes sharing rows: xor 1,2) + atomics ----
    #pragma unroll
    for (int r = 0; r < 8; ++r) {
        ap[r] = fmaxf(ap[r], __shfl_xor_sync(0xffffffffu, ap[r], 1));
        ap[r] = fmaxf(ap[r], __shfl_xor_sync(0xffffffffu, ap[r], 2));
        an[r] = fminf(an[r], __shfl_xor_sync(0xffffffffu, an[r], 1));
        an[r] = fminf(an[r], __shfl_xor_sync(0xffffffffu, an[r], 2));
    }
    if ((lane & 3) == 0) {
        #pragma unroll
        for (int r = 0; r < 8; ++r) {
            int row = i0 + warp_m * 64 + (r >> 1) * 16 + (r & 1) * 8 + (lane >> 2);
            atomicMax(&g_ap[row], __float_as_uint(fmaxf(ap[r], 0.f)));
            atomicMin(&g_an[row], __float_as_uint(fmaxf(an[r], 0.f)));
        }
    }

    // ---- fused loss: last CTA, resets counters for graph replay ----
    __threadfence();
    __shared__ int is_last;
    __shared__ float red[NTHR];
    if (t == 0)
        is_last = (atomicAdd(&g_done, 1) == GRID - 1);
    __syncthreads();
    if (is_last) {
        float s = 0.f;
        for (int i = t; i < NP; i += NTHR) {
            float apv = __uint_as_float(__ldcg(&g_ap[i]));
            float anv = __uint_as_float(__ldcg(&g_an[i]));
            float dap = sqrtf(apv);
            float dan = (anv > 9e11f) ? 1e6f : sqrtf(anv);
            s += fmaxf(0.f, 0.3f - (dan - dap));
        }
        red[t] = s;
        __syncthreads();
        #pragma unroll
        for (int m = NTHR / 2; m; m >>= 1) {
            if (t < m) red[t] += red[t + m];
            __syncthreads();
        }
        if (t == 0) {
            out[0]  = red[0] * (1.0f / (float)NP);
            g_done  = 0;
            g_gsync = 0;
        }
    }
}

// ---------- launch ----------
extern "C" void kernel_launch(void* const* d_in, const int* in_sizes, int n_in,
                              void* d_out, int out_size) {
    const float* feat = (const float*)d_in[0];
    const int*   lab  = (const int*)d_in[1];
    float*       out  = (float*)d_out;
    (void)in_sizes; (void)n_in; (void)out_size;

    const int smem_bytes = 98304 + 2048;   // 100352
    cudaFuncSetAttribute(triplet_mma,
                         cudaFuncAttributeMaxDynamicSharedMemorySize,
                         smem_bytes);

    prep_all<<<GRID, NTHR>>>(feat, lab);
    triplet_mma<<<GRID, NTHR, smem_bytes>>>(out);
}

// round 15
// speedup vs baseline: 1.0605x; 1.0605x over previous
#include <cuda_runtime.h>
#include <cuda_fp16.h>
#include <cstdint>

#define NP 8192
#define DK 128
#define NTHR 256
#define GRID 256

__device__ __half   g_afrag[NP * DK];
__device__ __half   g_bfrag[NP * DK];
__device__ float2   g_meta[NP];         // (sq_norm, label) — label-sorted order
__device__ unsigned g_ap[NP];
__device__ unsigned g_an[NP];
__device__ int      g_done = 0;

// ---------- helpers ----------
__device__ __forceinline__ uint32_t smem_u32(const void* p) {
    uint32_t a;
    asm("{ .reg .u64 t; cvta.to.shared.u64 t, %1; cvt.u32.u64 %0, t; }"
        : "=r"(a) : "l"(p));
    return a;
}
__device__ __forceinline__ void cp16(uint32_t dst, const void* src) {
    asm volatile("cp.async.cg.shared.global [%0], [%1], 16;" :: "r"(dst), "l"(src));
}
__device__ __forceinline__ void cp8(uint32_t dst, const void* src) {
    asm volatile("cp.async.ca.shared.global [%0], [%1], 8;" :: "r"(dst), "l"(src));
}
#define CP_COMMIT() asm volatile("cp.async.commit_group;" ::: "memory")

__device__ __forceinline__ void mma_f16(float* d, const uint4& a, const uint2& b) {
    asm volatile(
        "mma.sync.aligned.m16n8k16.row.col.f32.f16.f16.f32 "
        "{%0,%1,%2,%3}, {%4,%5,%6,%7}, {%8,%9}, {%0,%1,%2,%3};"
        : "+f"(d[0]), "+f"(d[1]), "+f"(d[2]), "+f"(d[3])
        : "r"(a.x), "r"(a.y), "r"(a.z), "r"(a.w), "r"(b.x), "r"(b.y));
}

// ---------- sync-free prep: detect + rank-sort + frag scatter ----------
// Each CTA handles 32 rows. Destination of row r = rank of (label, idx)
// over all 8192 rows — computed locally from an smem copy of all labels.
__global__ void __launch_bounds__(NTHR, 2)
prep_all(const float* __restrict__ f, const int* __restrict__ lab) {
    __shared__ int slab[NP];     // 32 KB: all labels
    __shared__ int sdst[32];

    const int t = threadIdx.x, lane = t & 31, wid = t >> 5;
    const int cta = blockIdx.x;

    // label-layout detection (identical result in every CTA)
    int nz = (lab[2 * t + 1] != 0);
    const int l64 = !__syncthreads_or(nz);

    // load all labels into smem
    for (int i = t; i < NP; i += NTHR)
        slab[i] = lab[l64 ? (i << 1) : i];
    __syncthreads();

    // rank computation: 8 threads per row, each scans one 1024-label segment
    {
        const int rloc = t >> 3;             // 0..31
        const int seg  = t & 7;              // 0..7
        const int row  = cta * 32 + rloc;
        const int lr   = slab[row];
        const int4* sl4 = (const int4*)slab; // 2048 int4
        const int base4 = seg * 256;
        int cnt = 0;
        #pragma unroll 4
        for (int i = 0; i < 256; ++i) {
            int idx4 = base4 + ((i + seg) & 255);   // phase rotation: no conflicts
            int4 v = sl4[idx4];
            int gx = idx4 * 4;
            cnt += (v.x < lr) + ((v.x == lr) & (gx     < row));
            cnt += (v.y < lr) + ((v.y == lr) & (gx + 1 < row));
            cnt += (v.z < lr) + ((v.z == lr) & (gx + 2 < row));
            cnt += (v.w < lr) + ((v.w == lr) & (gx + 3 < row));
        }
        cnt += __shfl_xor_sync(0xffffffffu, cnt, 1);
        cnt += __shfl_xor_sync(0xffffffffu, cnt, 2);
        cnt += __shfl_xor_sync(0xffffffffu, cnt, 4);
        if ((t & 7) == 0) sdst[rloc] = cnt;
    }
    __syncthreads();

    // scatter: warp per row (4 rows per warp)
    #pragma unroll
    for (int q = 0; q < 4; ++q) {
        const int rloc = wid * 4 + q;
        const int row  = cta * 32 + rloc;
        const int li   = slab[row];
        const int dst  = sdst[rloc];
        const float* p = f + (size_t)row * DK;

        const int tile = dst >> 7;
        const int n    = dst & 127;
        char* abase = (char*)g_afrag + (size_t)tile * 32768;
        char* bbase = (char*)g_bfrag + (size_t)tile * 32768;
        const int wm = n >> 6, mfrag = (n >> 4) & 3, r16 = n & 15;
        const int wn = n >> 5, nfrag = (n >> 3) & 3, nn = n & 7;

        float s = 0.f;
        #pragma unroll
        for (int u = 0; u < 4; ++u) {
            int k = lane + u * 32;
            float v = p[k];
            s += v * v;
            __half hv = __float2half_rn(v);
            int ks = k >> 4, kk = k & 15;
            int lane_a = (r16 & 7) * 4 + ((kk & 7) >> 1);
            int reg_a  = ((kk >= 8) ? 2 : 0) + (r16 >> 3);
            *(__half*)(abase + ks * 4096 + wm * 2048 + mfrag * 512
                       + lane_a * 16 + reg_a * 4 + (kk & 1) * 2) = hv;
            int lane_b = nn * 4 + ((kk & 7) >> 1);
            int reg_b  = (kk >= 8) ? 1 : 0;
            *(__half*)(bbase + ks * 4096 + wn * 1024 + nfrag * 256
                       + lane_b * 8 + reg_b * 4 + (kk & 1) * 2) = hv;
        }
        #pragma unroll
        for (int m = 16; m; m >>= 1) s += __shfl_xor_sync(0xffffffffu, s, m);
        if (lane == 0) {
            g_meta[dst] = make_float2(s, (float)li);
            g_ap[dst] = 0u;
            g_an[dst] = __float_as_uint(1e12f);
        }
    }
}

// ---------- main fused fp16-MMA kernel (R13 champion, unchanged) ----------
// grid = 64 it x 4 d-groups. Tile (it, jt=(it+d)&63), upper triangle once.
__global__ void __launch_bounds__(NTHR, 2)
triplet_mma(float* __restrict__ out) {
    extern __shared__ char smem[];
    char*   sA  = smem;                        // 32768
    char*   sB  = smem + 32768;                // 2 x 32768
    float2* sMB = (float2*)(smem + 98304);     // 2 x 128 float2
    const uint32_t sAu  = smem_u32(sA);
    const uint32_t sBu  = smem_u32(sB);
    const uint32_t sMBu = smem_u32(sMB);

    const int t = threadIdx.x, lane = t & 31, wid = t >> 5;
    const int warp_m = wid >> 2, warp_n = wid & 3;
    const int it = blockIdx.x >> 2, g = blockIdx.x & 3;
    const int i0 = it * 128;
    const int d0 = g * 8;
    const int nd = 8 + ((g == 3 && it < 32) ? 1 : 0);

    {
        const uint4* as = (const uint4*)((const char*)g_afrag + (size_t)it * 32768);
        #pragma unroll
        for (int u = 0; u < 8; ++u)
            cp16(sAu + (t + u * 256) * 16, as + t + u * 256);
        int jt = (it + d0) & 63;
        const uint4* bs = (const uint4*)((const char*)g_bfrag + (size_t)jt * 32768);
        #pragma unroll
        for (int u = 0; u < 8; ++u)
            cp16(sBu + (t + u * 256) * 16, bs + t + u * 256);
        if (t < 128) cp8(sMBu + t * 8, &g_meta[jt * 128 + t]);
        CP_COMMIT();
    }

    const float minI = g_meta[i0].y;
    const float maxI = g_meta[i0 + 127].y;

    float rsq[8], rlab[8];
    #pragma unroll
    for (int mf = 0; mf < 4; ++mf)
        #pragma unroll
        for (int rr = 0; rr < 2; ++rr) {
            float2 m = g_meta[i0 + warp_m * 64 + mf * 16 + rr * 8 + (lane >> 2)];
            rsq[mf * 2 + rr]  = m.x;
            rlab[mf * 2 + rr] = m.y;
        }

    float ap[8], an[8];
    #pragma unroll
    for (int r = 0; r < 8; ++r) { ap[r] = 0.f; an[r] = 1e12f; }

    for (int s = 0; s < nd; ++s) {
        const int d   = d0 + s;
        const int jt  = (it + d) & 63;
        const int buf = s & 1;

        asm volatile("cp.async.wait_group 0;" ::: "memory");
        __syncthreads();

        if (s + 1 < nd) {
            int jn = (it + d + 1) & 63;
            const uint4* bs = (const uint4*)((const char*)g_bfrag + (size_t)jn * 32768);
            uint32_t bd = sBu + (uint32_t)(buf ^ 1) * 32768u;
            #pragma unroll
            for (int u = 0; u < 8; ++u)
                cp16(bd + (t + u * 256) * 16, bs + t + u * 256);
            if (t < 128)
                cp8(sMBu + (buf ^ 1) * 1024 + t * 8, &g_meta[jn * 128 + t]);
            CP_COMMIT();
        }

        float acc[4][4][4];
        #pragma unroll
        for (int mf = 0; mf < 4; ++mf)
            #pragma unroll
            for (int nf = 0; nf < 4; ++nf)
                #pragma unroll
                for (int e = 0; e < 4; ++e) acc[mf][nf][e] = 0.f;

        const uint4* Af = (const uint4*)sA + warp_m * 128;
        const uint2* Bf = (const uint2*)(sB + buf * 32768) + warp_n * 128;
        #pragma unroll
        for (int ks = 0; ks < 8; ++ks) {
            uint4 a[4]; uint2 b[4];
            #pragma unroll
            for (int mf = 0; mf < 4; ++mf) a[mf] = Af[ks * 256 + mf * 32 + lane];
            #pragma unroll
            for (int nf = 0; nf < 4; ++nf) b[nf] = Bf[ks * 512 + nf * 32 + lane];
            #pragma unroll
            for (int mf = 0; mf < 4; ++mf)
                #pragma unroll
                for (int nf = 0; nf < 4; ++nf)
                    mma_f16(acc[mf][nf], a[mf], b[nf]);
        }

        const float2* MB = sMB + buf * 128;
        const int jg0 = jt * 128;
        const float minJ = MB[0].y, maxJ = MB[127].y;
        const bool dirty = (d == 0) || !((maxI < minJ) || (maxJ < minI));

        if (!dirty) {
            #pragma unroll
            for (int nf = 0; nf < 4; ++nf) {
                const int cl = warp_n * 32 + nf * 8 + (lane & 3) * 2;
                const float s0 = MB[cl].x;
                const float s1 = MB[cl + 1].x;
                float can0 = 1e12f, can1 = 1e12f;
                #pragma unroll
                for (int mf = 0; mf < 4; ++mf)
                    #pragma unroll
                    for (int rr = 0; rr < 2; ++rr) {
                        const int r = mf * 2 + rr;
                        float d20 = fmaf(-2.f, acc[mf][nf][rr * 2 + 0], rsq[r] + s0);
                        float d21 = fmaf(-2.f, acc[mf][nf][rr * 2 + 1], rsq[r] + s1);
                        an[r] = fminf(an[r], fminf(d20, d21));
                        can0  = fminf(can0, d20);
                        can1  = fminf(can1, d21);
                    }
                #pragma unroll
                for (int m = 4; m <= 16; m <<= 1) {
                    can0 = fminf(can0, __shfl_xor_sync(0xffffffffu, can0, m));
                    can1 = fminf(can1, __shfl_xor_sync(0xffffffffu, can1, m));
                }
                if (lane < 4) {
                    atomicMin(&g_an[jg0 + cl],     __float_as_uint(fmaxf(can0, 0.f)));
                    atomicMin(&g_an[jg0 + cl + 1], __float_as_uint(fmaxf(can1, 0.f)));
                }
            }
        } else if (d != 0) {
            #pragma unroll
            for (int nf = 0; nf < 4; ++nf) {
                const int cl = warp_n * 32 + nf * 8 + (lane & 3) * 2;
                const float2 m0 = MB[cl];
                const float2 m1 = MB[cl + 1];
                float cap0 = 0.f, can0 = 1e12f, cap1 = 0.f, can1 = 1e12f;
                #pragma unroll
                for (int mf = 0; mf < 4; ++mf)
                    #pragma unroll
                    for (int rr = 0; rr < 2; ++rr) {
                        const int r = mf * 2 + rr;
                        float d20 = fmaf(-2.f, acc[mf][nf][rr * 2 + 0], rsq[r] + m0.x);
                        float d21 = fmaf(-2.f, acc[mf][nf][rr * 2 + 1], rsq[r] + m1.x);
                        bool p0 = (rlab[r] == m0.y);
                        bool p1 = (rlab[r] == m1.y);
                        ap[r] = p0 ? fmaxf(ap[r], d20) : ap[r];
                        an[r] = p0 ? an[r] : fminf(an[r], d20);
                        cap0  = p0 ? fmaxf(cap0, d20) : cap0;
                        can0  = p0 ? can0 : fminf(can0, d20);
                        ap[r] = p1 ? fmaxf(ap[r], d21) : ap[r];
                        an[r] = p1 ? an[r] : fminf(an[r], d21);
                        cap1  = p1 ? fmaxf(cap1, d21) : cap1;
                        can1  = p1 ? can1 : fminf(can1, d21);
                    }
                #pragma unroll
                for (int m = 4; m <= 16; m <<= 1) {
                    cap0 = fmaxf(cap0, __shfl_xor_sync(0xffffffffu, cap0, m));
                    can0 = fminf(can0, __shfl_xor_sync(0xffffffffu, can0, m));
                    cap1 = fmaxf(cap1, __shfl_xor_sync(0xffffffffu, cap1, m));
                    can1 = fminf(can1, __shfl_xor_sync(0xffffffffu, can1, m));
                }
                if (lane < 4) {
                    atomicMax(&g_ap[jg0 + cl],     __float_as_uint(fmaxf(cap0, 0.f)));
                    atomicMin(&g_an[jg0 + cl],     __float_as_uint(fmaxf(can0, 0.f)));
                    atomicMax(&g_ap[jg0 + cl + 1], __float_as_uint(fmaxf(cap1, 0.f)));
                    atomicMin(&g_an[jg0 + cl + 1], __float_as_uint(fmaxf(can1, 0.f)));
                }
            }
        } else {
            #pragma unroll
            for (int nf = 0; nf < 4; ++nf) {
                const int cl = warp_n * 32 + nf * 8 + (lane & 3) * 2;
                const float2 m0 = MB[cl];
                const float2 m1 = MB[cl + 1];
                #pragma unroll
                for (int mf = 0; mf < 4; ++mf)
                    #pragma unroll
                    for (int rr = 0; rr < 2; ++rr) {
                        const int r = mf * 2 + rr;
                        const int ri = warp_m * 64 + mf * 16 + rr * 8 + (lane >> 2);
                        float d20 = fmaf(-2.f, acc[mf][nf][rr * 2 + 0], rsq[r] + m0.x);
                        float d21 = fmaf(-2.f, acc[mf][nf][rr * 2 + 1], rsq[r] + m1.x);
                        if (rlab[r] == m0.y) {
                            if (ri != cl) ap[r] = fmaxf(ap[r], d20);
                        } else an[r] = fminf(an[r], d20);
                        if (rlab[r] == m1.y) {
                            if (ri != cl + 1) ap[r] = fmaxf(ap[r], d21);
                        } else an[r] = fminf(an[r], d21);
                    }
            }
        }
    }

    // ---- row-stat reduce + atomics ----
    #pragma unroll
    for (int r = 0; r < 8; ++r) {
        ap[r] = fmaxf(ap[r], __shfl_xor_sync(0xffffffffu, ap[r], 1));
        ap[r] = fmaxf(ap[r], __shfl_xor_sync(0xffffffffu, ap[r], 2));
        an[r] = fminf(an[r], __shfl_xor_sync(0xffffffffu, an[r], 1));
        an[r] = fminf(an[r], __shfl_xor_sync(0xffffffffu, an[r], 2));
    }
    if ((lane & 3) == 0) {
        #pragma unroll
        for (int r = 0; r < 8; ++r) {
            int row = i0 + warp_m * 64 + (r >> 1) * 16 + (r & 1) * 8 + (lane >> 2);
            atomicMax(&g_ap[row], __float_as_uint(fmaxf(ap[r], 0.f)));
            atomicMin(&g_an[row], __float_as_uint(fmaxf(an[r], 0.f)));
        }
    }

    // ---- fused loss: last CTA, resets counter for graph replay ----
    __threadfence();
    __shared__ int is_last;
    __shared__ float red[NTHR];
    if (t == 0)
        is_last = (atomicAdd(&g_done, 1) == GRID - 1);
    __syncthreads();
    if (is_last) {
        float s = 0.f;
        for (int i = t; i < NP; i += NTHR) {
            float apv = __uint_as_float(__ldcg(&g_ap[i]));
            float anv = __uint_as_float(__ldcg(&g_an[i]));
            float dap = sqrtf(apv);
            float dan = (anv > 9e11f) ? 1e6f : sqrtf(anv);
            s += fmaxf(0.f, 0.3f - (dan - dap));
        }
        red[t] = s;
        __syncthreads();
        #pragma unroll
        for (int m = NTHR / 2; m; m >>= 1) {
            if (t < m) red[t] += red[t + m];
            __syncthreads();
        }
        if (t == 0) {
            out[0] = red[0] * (1.0f / (float)NP);
            g_done = 0;
        }
    }
}

// ---------- launch ----------
extern "C" void kernel_launch(void* const* d_in, const int* in_sizes, int n_in,
                              void* d_out, int out_size) {
    const float* feat = (const float*)d_in[0];
    const int*   lab  = (const int*)d_in[1];
    float*       out  = (float*)d_out;
    (void)in_sizes; (void)n_in; (void)out_size;

    const int smem_bytes = 98304 + 2048;   // 100352
    cudaFuncSetAttribute(triplet_mma,
                         cudaFuncAttributeMaxDynamicSharedMemorySize,
                         smem_bytes);

    prep_all<<<GRID, NTHR>>>(feat, lab);
    triplet_mma<<<GRID, NTHR, smem_bytes>>>(out);
}

// round 16
// speedup vs baseline: 1.4697x; 1.3859x over previous
#include <cuda_runtime.h>
#include <cuda_fp16.h>
#include <cstdint>

#define NP 8192
#define DK 128
#define NTHR 256
#define NLAB 512
#define GRID_P 256
#define NUNITS 2080   // 64 diag-mapped i-tiles x (32 or 33) d-units

__device__ __half   g_afrag[NP * DK];
__device__ __half   g_bfrag[NP * DK];
__device__ float2   g_meta[NP];         // (sq_norm, label) — label-sorted order
__device__ unsigned g_ap[NP];
__device__ unsigned g_an[NP];
__device__ int      g_bins[NLAB];
__device__ int      g_cursor[NLAB];
__device__ int      g_gsync = 0;
__device__ int      g_done  = 0;

// ---------- helpers ----------
__device__ __forceinline__ uint32_t smem_u32(const void* p) {
    uint32_t a;
    asm("{ .reg .u64 t; cvta.to.shared.u64 t, %1; cvt.u32.u64 %0, t; }"
        : "=r"(a) : "l"(p));
    return a;
}
__device__ __forceinline__ void cp16(uint32_t dst, const void* src) {
    asm volatile("cp.async.cg.shared.global [%0], [%1], 16;" :: "r"(dst), "l"(src));
}
__device__ __forceinline__ void cp8(uint32_t dst, const void* src) {
    asm volatile("cp.async.ca.shared.global [%0], [%1], 8;" :: "r"(dst), "l"(src));
}
#define CP_COMMIT() asm volatile("cp.async.commit_group;" ::: "memory")

__device__ __forceinline__ void mma_f16(float* d, const uint4& a, const uint2& b) {
    asm volatile(
        "mma.sync.aligned.m16n8k16.row.col.f32.f16.f16.f32 "
        "{%0,%1,%2,%3}, {%4,%5,%6,%7}, {%8,%9}, {%0,%1,%2,%3};"
        : "+f"(d[0]), "+f"(d[1]), "+f"(d[2]), "+f"(d[3])
        : "r"(a.x), "r"(a.y), "r"(a.z), "r"(a.w), "r"(b.x), "r"(b.y));
}

__device__ __forceinline__ void grid_sync(int target) {
    __syncthreads();
    if (threadIdx.x == 0) {
        __threadfence();
        atomicAdd(&g_gsync, 1);
        while (atomicAdd(&g_gsync, 0) < target) { }
    }
    __syncthreads();
}

__device__ __forceinline__ void decode_unit(int u, int& it, int& d) {
    if (u < 1056) { it = u / 33; d = u - it * 33; }
    else          { int v = u - 1056; it = 32 + (v >> 5); d = v & 31; }
}

// ---------- persistent prep: detect + hist + scan + counting-sort scatter ----------
__global__ void __launch_bounds__(NTHR, 2)
prep_all(const float* __restrict__ f, const int* __restrict__ lab) {
    const int t = threadIdx.x, lane = t & 31, wid = t >> 5;
    const int cta = blockIdx.x;

    int nz = (lab[2 * t + 1] != 0);
    const int l64 = !__syncthreads_or(nz);

    if (t < 32) {
        int row = cta * 32 + t;
        atomicAdd(&g_bins[lab[l64 ? (row << 1) : row]], 1);
    }
    grid_sync(GRID_P);

    if (cta == 0) {
        __shared__ int wsum[8];
        int b0 = g_bins[2 * t], b1 = g_bins[2 * t + 1];
        int ps = b0 + b1;
        int x = ps;
        #pragma unroll
        for (int m = 1; m < 32; m <<= 1) {
            int y = __shfl_up_sync(0xffffffffu, x, m);
            if (lane >= m) x += y;
        }
        if (lane == 31) wsum[wid] = x;
        __syncthreads();
        if (t == 0) {
            int acc = 0;
            #pragma unroll
            for (int q = 0; q < 8; ++q) { int v = wsum[q]; wsum[q] = acc; acc += v; }
        }
        __syncthreads();
        int excl = x - ps + wsum[wid];
        g_cursor[2 * t]     = excl;
        g_cursor[2 * t + 1] = excl + b0;
        g_bins[2 * t] = 0; g_bins[2 * t + 1] = 0;
    }
    grid_sync(2 * GRID_P);

    #pragma unroll
    for (int q = 0; q < 4; ++q) {
        int row = cta * 32 + wid * 4 + q;
        const float* p = f + (size_t)row * DK;
        int li = 0, dst = 0;
        if (lane == 0) {
            li  = lab[l64 ? (row << 1) : row];
            dst = atomicAdd(&g_cursor[li], 1);
        }
        li  = __shfl_sync(0xffffffffu, li, 0);
        dst = __shfl_sync(0xffffffffu, dst, 0);

        const int tile = dst >> 7;
        const int n    = dst & 127;
        char* abase = (char*)g_afrag + (size_t)tile * 32768;
        char* bbase = (char*)g_bfrag + (size_t)tile * 32768;
        const int wm = n >> 6, mfrag = (n >> 4) & 3, r16 = n & 15;
        const int wn = n >> 5, nfrag = (n >> 3) & 3, nn = n & 7;

        float s = 0.f;
        #pragma unroll
        for (int u = 0; u < 4; ++u) {
            int k = lane + u * 32;
            float v = p[k];
            s += v * v;
            __half hv = __float2half_rn(v);
            int ks = k >> 4, kk = k & 15;
            int lane_a = (r16 & 7) * 4 + ((kk & 7) >> 1);
            int reg_a  = ((kk >= 8) ? 2 : 0) + (r16 >> 3);
            *(__half*)(abase + ks * 4096 + wm * 2048 + mfrag * 512
                       + lane_a * 16 + reg_a * 4 + (kk & 1) * 2) = hv;
            int lane_b = nn * 4 + ((kk & 7) >> 1);
            int reg_b  = (kk >= 8) ? 1 : 0;
            *(__half*)(bbase + ks * 4096 + wn * 1024 + nfrag * 256
                       + lane_b * 8 + reg_b * 4 + (kk & 1) * 2) = hv;
        }
        #pragma unroll
        for (int m = 16; m; m >>= 1) s += __shfl_xor_sync(0xffffffffu, s, m);
        if (lane == 0) {
            g_meta[dst] = make_float2(s, (float)li);
            g_ap[dst] = 0u;
            g_an[dst] = __float_as_uint(1e12f);
        }
    }
}

// ---------- main kernel: flattened symmetric units over 2*numSM CTAs ----------
__global__ void __launch_bounds__(NTHR, 2)
triplet_mma(float* __restrict__ out) {
    extern __shared__ char smem[];
    char*   sA  = smem;                        // 32768
    char*   sB  = smem + 32768;                // 2 x 32768
    float2* sMB = (float2*)(smem + 98304);     // 2 x 128 float2
    const uint32_t sAu  = smem_u32(sA);
    const uint32_t sBu  = smem_u32(sB);
    const uint32_t sMBu = smem_u32(sMB);

    const int t = threadIdx.x, lane = t & 31, wid = t >> 5;
    const int warp_m = wid >> 2, warp_n = wid & 3;
    const int nct = gridDim.x;
    const int u0 = (int)(((long long)blockIdx.x * NUNITS) / nct);
    const int u1 = (int)(((long long)(blockIdx.x + 1) * NUNITS) / nct);

    // prologue: A(it of u0) + B(u0) + metaB
    {
        int it0, d0x; decode_unit(u0, it0, d0x);
        int jt0 = (it0 + d0x) & 63;
        const uint4* as = (const uint4*)((const char*)g_afrag + (size_t)it0 * 32768);
        #pragma unroll
        for (int u = 0; u < 8; ++u)
            cp16(sAu + (t + u * 256) * 16, as + t + u * 256);
        const uint4* bs = (const uint4*)((const char*)g_bfrag + (size_t)jt0 * 32768);
        uint32_t bd = sBu + (uint32_t)(u0 & 1) * 32768u;
        #pragma unroll
        for (int u = 0; u < 8; ++u)
            cp16(bd + (t + u * 256) * 16, bs + t + u * 256);
        if (t < 128) cp8(sMBu + (u0 & 1) * 1024 + t * 8, &g_meta[jt0 * 128 + t]);
        CP_COMMIT();
    }

    int   cur_it = -1, i0 = 0;
    float minI = 0.f, maxI = 0.f;
    float rsq[8], rlab[8], ap[8], an[8];

    #define FLUSH_ROWS() do {                                                \
        _Pragma("unroll")                                                    \
        for (int r = 0; r < 8; ++r) {                                        \
            ap[r] = fmaxf(ap[r], __shfl_xor_sync(0xffffffffu, ap[r], 1));    \
            ap[r] = fmaxf(ap[r], __shfl_xor_sync(0xffffffffu, ap[r], 2));    \
            an[r] = fminf(an[r], __shfl_xor_sync(0xffffffffu, an[r], 1));    \
            an[r] = fminf(an[r], __shfl_xor_sync(0xffffffffu, an[r], 2));    \
        }                                                                    \
        if ((lane & 3) == 0) {                                               \
            _Pragma("unroll")                                                \
            for (int r = 0; r < 8; ++r) {                                    \
                int row = i0 + warp_m * 64 + (r >> 1) * 16 + (r & 1) * 8     \
                          + (lane >> 2);                                     \
                atomicMax(&g_ap[row], __float_as_uint(fmaxf(ap[r], 0.f)));   \
                atomicMin(&g_an[row], __float_as_uint(fmaxf(an[r], 0.f)));   \
            }                                                                \
        }                                                                    \
    } while (0)

    for (int u = u0; u < u1; ++u) {
        int it, d; decode_unit(u, it, d);
        const int jt  = (it + d) & 63;
        const int buf = u & 1;
        const bool newit = (it != cur_it);

        asm volatile("cp.async.wait_group 0;" ::: "memory");
        __syncthreads();

        if (newit && cur_it >= 0) {
            FLUSH_ROWS();
        }
        if (newit && u != u0) {
            const uint4* as = (const uint4*)((const char*)g_afrag + (size_t)it * 32768);
            #pragma unroll
            for (int q = 0; q < 8; ++q)
                cp16(sAu + (t + q * 256) * 16, as + t + q * 256);
            CP_COMMIT();
        }
        if (u + 1 < u1) {
            int itn, dn; decode_unit(u + 1, itn, dn);
            int jn = (itn + dn) & 63;
            const uint4* bs = (const uint4*)((const char*)g_bfrag + (size_t)jn * 32768);
            uint32_t bd = sBu + (uint32_t)(buf ^ 1) * 32768u;
            #pragma unroll
            for (int q = 0; q < 8; ++q)
                cp16(bd + (t + q * 256) * 16, bs + t + q * 256);
            if (t < 128)
                cp8(sMBu + (buf ^ 1) * 1024 + t * 8, &g_meta[jn * 128 + t]);
            CP_COMMIT();
        }
        if (newit) {
            if (u != u0) {
                if (u + 1 < u1) asm volatile("cp.async.wait_group 1;" ::: "memory");
                else            asm volatile("cp.async.wait_group 0;" ::: "memory");
                __syncthreads();
            }
            cur_it = it;
            i0 = it * 128;
            minI = g_meta[i0].y;
            maxI = g_meta[i0 + 127].y;
            #pragma unroll
            for (int mf = 0; mf < 4; ++mf)
                #pragma unroll
                for (int rr = 0; rr < 2; ++rr) {
                    float2 m = g_meta[i0 + warp_m * 64 + mf * 16 + rr * 8 + (lane >> 2)];
                    rsq[mf * 2 + rr]  = m.x;
                    rlab[mf * 2 + rr] = m.y;
                }
            #pragma unroll
            for (int r = 0; r < 8; ++r) { ap[r] = 0.f; an[r] = 1e12f; }
        }

        // ---- MMA over K=128 (8 k16-steps), 4 m-frags x 4 n-frags ----
        float acc[4][4][4];
        #pragma unroll
        for (int mf = 0; mf < 4; ++mf)
            #pragma unroll
            for (int nf = 0; nf < 4; ++nf)
                #pragma unroll
                for (int e = 0; e < 4; ++e) acc[mf][nf][e] = 0.f;

        const uint4* Af = (const uint4*)sA + warp_m * 128;
        const uint2* Bf = (const uint2*)(sB + buf * 32768) + warp_n * 128;
        #pragma unroll
        for (int ks = 0; ks < 8; ++ks) {
            uint4 a[4]; uint2 b[4];
            #pragma unroll
            for (int mf = 0; mf < 4; ++mf) a[mf] = Af[ks * 256 + mf * 32 + lane];
            #pragma unroll
            for (int nf = 0; nf < 4; ++nf) b[nf] = Bf[ks * 512 + nf * 32 + lane];
            #pragma unroll
            for (int mf = 0; mf < 4; ++mf)
                #pragma unroll
                for (int nf = 0; nf < 4; ++nf)
                    mma_f16(acc[mf][nf], a[mf], b[nf]);
        }

        const float2* MB = sMB + buf * 128;
        const int jg0 = jt * 128;
        const float minJ = MB[0].y, maxJ = MB[127].y;
        const bool dirty = (d == 0) || !((maxI < minJ) || (maxJ < minI));

        if (!dirty) {
            #pragma unroll
            for (int nf = 0; nf < 4; ++nf) {
                const int cl = warp_n * 32 + nf * 8 + (lane & 3) * 2;
                const float s0 = MB[cl].x;
                const float s1 = MB[cl + 1].x;
                float can0 = 1e12f, can1 = 1e12f;
                #pragma unroll
                for (int mf = 0; mf < 4; ++mf)
                    #pragma unroll
                    for (int rr = 0; rr < 2; ++rr) {
                        const int r = mf * 2 + rr;
                        float d20 = fmaf(-2.f, acc[mf][nf][rr * 2 + 0], rsq[r] + s0);
                        float d21 = fmaf(-2.f, acc[mf][nf][rr * 2 + 1], rsq[r] + s1);
                        an[r] = fminf(an[r], fminf(d20, d21));
                        can0  = fminf(can0, d20);
                        can1  = fminf(can1, d21);
                    }
                #pragma unroll
                for (int m = 4; m <= 16; m <<= 1) {
                    can0 = fminf(can0, __shfl_xor_sync(0xffffffffu, can0, m));
                    can1 = fminf(can1, __shfl_xor_sync(0xffffffffu, can1, m));
                }
                if (lane < 4) {
                    atomicMin(&g_an[jg0 + cl],     __float_as_uint(fmaxf(can0, 0.f)));
                    atomicMin(&g_an[jg0 + cl + 1], __float_as_uint(fmaxf(can1, 0.f)));
                }
            }
        } else if (d != 0) {
            #pragma unroll
            for (int nf = 0; nf < 4; ++nf) {
                const int cl = warp_n * 32 + nf * 8 + (lane & 3) * 2;
                const float2 m0 = MB[cl];
                const float2 m1 = MB[cl + 1];
                float cap0 = 0.f, can0 = 1e12f, cap1 = 0.f, can1 = 1e12f;
                #pragma unroll
                for (int mf = 0; mf < 4; ++mf)
                    #pragma unroll
                    for (int rr = 0; rr < 2; ++rr) {
                        const int r = mf * 2 + rr;
                        float d20 = fmaf(-2.f, acc[mf][nf][rr * 2 + 0], rsq[r] + m0.x);
                        float d21 = fmaf(-2.f, acc[mf][nf][rr * 2 + 1], rsq[r] + m1.x);
                        bool p0 = (rlab[r] == m0.y);
                        bool p1 = (rlab[r] == m1.y);
                        ap[r] = p0 ? fmaxf(ap[r], d20) : ap[r];
                        an[r] = p0 ? an[r] : fminf(an[r], d20);
                        cap0  = p0 ? fmaxf(cap0, d20) : cap0;
                        can0  = p0 ? can0 : fminf(can0, d20);
                        ap[r] = p1 ? fmaxf(ap[r], d21) : ap[r];
                        an[r] = p1 ? an[r] : fminf(an[r], d21);
                        cap1  = p1 ? fmaxf(cap1, d21) : cap1;
                        can1  = p1 ? can1 : fminf(can1, d21);
                    }
                #pragma unroll
                for (int m = 4; m <= 16; m <<= 1) {
                    cap0 = fmaxf(cap0, __shfl_xor_sync(0xffffffffu, cap0, m));
                    can0 = fminf(can0, __shfl_xor_sync(0xffffffffu, can0, m));
                    cap1 = fmaxf(cap1, __shfl_xor_sync(0xffffffffu, cap1, m));
                    can1 = fminf(can1, __shfl_xor_sync(0xffffffffu, can1, m));
                }
                if (lane < 4) {
                    atomicMax(&g_ap[jg0 + cl],     __float_as_uint(fmaxf(cap0, 0.f)));
                    atomicMin(&g_an[jg0 + cl],     __float_as_uint(fmaxf(can0, 0.f)));
                    atomicMax(&g_ap[jg0 + cl + 1], __float_as_uint(fmaxf(cap1, 0.f)));
                    atomicMin(&g_an[jg0 + cl + 1], __float_as_uint(fmaxf(can1, 0.f)));
                }
            }
        } else {
            #pragma unroll
            for (int nf = 0; nf < 4; ++nf) {
                const int cl = warp_n * 32 + nf * 8 + (lane & 3) * 2;
                const float2 m0 = MB[cl];
                const float2 m1 = MB[cl + 1];
                #pragma unroll
                for (int mf = 0; mf < 4; ++mf)
                    #pragma unroll
                    for (int rr = 0; rr < 2; ++rr) {
                        const int r = mf * 2 + rr;
                        const int ri = warp_m * 64 + mf * 16 + rr * 8 + (lane >> 2);
                        float d20 = fmaf(-2.f, acc[mf][nf][rr * 2 + 0], rsq[r] + m0.x);
                        float d21 = fmaf(-2.f, acc[mf][nf][rr * 2 + 1], rsq[r] + m1.x);
                        if (rlab[r] == m0.y) {
                            if (ri != cl) ap[r] = fmaxf(ap[r], d20);
                        } else an[r] = fminf(an[r], d20);
                        if (rlab[r] == m1.y) {
                            if (ri != cl + 1) ap[r] = fmaxf(ap[r], d21);
                        } else an[r] = fminf(an[r], d21);
                    }
            }
        }
    }

    if (cur_it >= 0) FLUSH_ROWS();
    #undef FLUSH_ROWS

    // ---- fused loss: last CTA, resets counters for graph replay ----
    __threadfence();
    __shared__ int is_last;
    __shared__ float red[NTHR];
    if (t == 0)
        is_last = (atomicAdd(&g_done, 1) == nct - 1);
    __syncthreads();
    if (is_last) {
        float s = 0.f;
        for (int i = t; i < NP; i += NTHR) {
            float apv = __uint_as_float(__ldcg(&g_ap[i]));
            float anv = __uint_as_float(__ldcg(&g_an[i]));
            float dap = sqrtf(apv);
            float dan = (anv > 9e11f) ? 1e6f : sqrtf(anv);
            s += fmaxf(0.f, 0.3f - (dan - dap));
        }
        red[t] = s;
        __syncthreads();
        #pragma unroll
        for (int m = NTHR / 2; m; m >>= 1) {
            if (t < m) red[t] += red[t + m];
            __syncthreads();
        }
        if (t == 0) {
            out[0]  = red[0] * (1.0f / (float)NP);
            g_done  = 0;
            g_gsync = 0;   // reset prep's sync counter for next graph replay
        }
    }
}

// ---------- launch ----------
extern "C" void kernel_launch(void* const* d_in, const int* in_sizes, int n_in,
                              void* d_out, int out_size) {
    const float* feat = (const float*)d_in[0];
    const int*   lab  = (const int*)d_in[1];
    float*       out  = (float*)d_out;
    (void)in_sizes; (void)n_in; (void)out_size;

    int sms = 0;
    cudaDeviceGetAttribute(&sms, cudaDevAttrMultiProcessorCount, 0);
    int grid = 2 * sms;                 // fully resident at 2 CTA/SM
    if (grid > NUNITS) grid = NUNITS;

    const int smem_bytes = 98304 + 2048;   // 100352
    cudaFuncSetAttribute(triplet_mma,
                         cudaFuncAttributeMaxDynamicSharedMemorySize,
                         smem_bytes);

    prep_all<<<GRID_P, NTHR>>>(feat, lab);
    triplet_mma<<<grid, NTHR, smem_bytes>>>(out);
}